// round 11
// baseline (speedup 1.0000x reference)
#include <cuda_runtime.h>
#include <cuda_bf16.h>
#include <stdint.h>
#include <math.h>

// Generator_causal via bf16 mma.sync, sync-free mainloop.
// R11: k-OUTER / j-INNER mma ordering -> same-accumulator dependency distance 16
// (was 1-2), hiding HMMA RAW latency. Everything else as R10:
// per-warp 32 rows, j-half C tiles, gmem fragment streams, z folded into fc epi.

#define XD 32
#define HD 128
#define TPB 128
#define ROWS 128

// smem: ZT [128][66B] z bf16 rows; OX [128][80B] o-state bf16 rows; MB [32][64B]
#define OFF_ZT 0
#define OFF_OX 8448
#define OFF_MB 18688
#define SMEM_BYTES 20736

// fragment images in global scratch (built by prep kernel)
__device__ uint2 g_WiF[32*16*2*32];   // [i][j][kk][lane] 256KB
__device__ uint4 g_W1F[16*4*32];      // [j][kkp][lane]   32KB
__device__ uint4 g_W2F[16*4*32];      // 32KB
__device__ float g_w32[32*128];       // Wi[:,32] per step 16KB

static __device__ __forceinline__ uint32_t pack_bf2(float lo, float hi){
    __nv_bfloat162 p = __floats2bfloat162_rn(lo, hi);
    return *(uint32_t*)&p;
}
static __device__ __forceinline__ uint32_t hmul2u(uint32_t a, uint32_t b){
    __nv_bfloat162 r = __hmul2(*(__nv_bfloat162*)&a, *(__nv_bfloat162*)&b);
    return *(uint32_t*)&r;
}
static __device__ __forceinline__ void mma_bf16(float* c, const uint32_t* a,
                                                uint32_t b0, uint32_t b1){
    asm volatile("mma.sync.aligned.m16n8k16.row.col.f32.bf16.bf16.f32 "
        "{%0,%1,%2,%3}, {%4,%5,%6,%7}, {%8,%9}, {%0,%1,%2,%3};"
        : "+f"(c[0]), "+f"(c[1]), "+f"(c[2]), "+f"(c[3])
        : "r"(a[0]), "r"(a[1]), "r"(a[2]), "r"(a[3]), "r"(b0), "r"(b1));
}
// zero-accumulator variant: writes C without reading it
static __device__ __forceinline__ void mma_bf16_z(float* c, const uint32_t* a,
                                                  uint32_t b0, uint32_t b1){
    float zz = 0.f;
    asm volatile("mma.sync.aligned.m16n8k16.row.col.f32.bf16.bf16.f32 "
        "{%0,%1,%2,%3}, {%4,%5,%6,%7}, {%8,%9}, {%10,%10,%10,%10};"
        : "=f"(c[0]), "=f"(c[1]), "=f"(c[2]), "=f"(c[3])
        : "r"(a[0]), "r"(a[1]), "r"(a[2]), "r"(a[3]), "r"(b0), "r"(b1), "f"(zz));
}

// ---------------- prep: bake fragment images ----------------
__global__ void prep_frag(const float* __restrict__ Wi,
                          const float* __restrict__ W1,
                          const float* __restrict__ W2){
    int idx = blockIdx.x * 256 + threadIdx.x;      // 32768 threads
    if (idx < 32*16*2*32){
        int lane = idx & 31, kk = (idx>>5)&1, j = (idx>>6)&15, i = idx>>10;
        int n = 8*j + (lane>>2), k0 = 16*kk + 2*(lane&3);
        const float* s = Wi + ((size_t)i*HD + n)*(XD+1);
        uint2 v;
        v.x = pack_bf2(s[k0],   s[k0+1]);
        v.y = pack_bf2(s[k0+8], s[k0+9]);
        g_WiF[idx] = v;
    }
    if (idx < 16*4*32){
        int lane = idx & 31, kkp = (idx>>5)&3, j = idx>>7;
        int n = 8*j + (lane>>2), kb = 32*kkp + 2*(lane&3);
        const float* s1 = W1 + n*HD;
        const float* s2 = W2 + n*HD;
        uint4 v1, v2;
        v1.x = pack_bf2(s1[kb],    s1[kb+1]);  v1.y = pack_bf2(s1[kb+8],  s1[kb+9]);
        v1.z = pack_bf2(s1[kb+16], s1[kb+17]); v1.w = pack_bf2(s1[kb+24], s1[kb+25]);
        v2.x = pack_bf2(s2[kb],    s2[kb+1]);  v2.y = pack_bf2(s2[kb+8],  s2[kb+9]);
        v2.z = pack_bf2(s2[kb+16], s2[kb+17]); v2.w = pack_bf2(s2[kb+24], s2[kb+25]);
        g_W1F[idx] = v1;
        g_W2F[idx] = v2;
    }
    if (idx < 32*128){
        int i = idx >> 7, n = idx & 127;
        g_w32[idx] = Wi[((size_t)i*HD + n)*(XD+1) + XD];
    }
}

// ---------------- main ----------------
__global__ void __launch_bounds__(TPB, 2) gen_causal_nf(
    const float* __restrict__ x,  const float* __restrict__ z,
    const float* __restrict__ M,
    const float* __restrict__ bi, const float* __restrict__ wf,
    const float* __restrict__ bf,
    const float* __restrict__ b1, const float* __restrict__ b2,
    float* __restrict__ out, int B)
{
    extern __shared__ char base[];
    char* ZTp = base + OFF_ZT;
    char* OXp = base + OFF_OX;
    char* MBp = base + OFF_MB;

    const int t    = threadIdx.x;
    const int lane = t & 31;
    const int warp = t >> 5;
    const int wbase = warp * 32;
    const int tq = lane & 3;
    const int g  = lane >> 2;
    const int ctaRow = blockIdx.x * ROWS;
    const int row = ctaRow + t;
    const bool active = (row < B);

    // ---- one-time init ----
    #pragma unroll 4
    for (int it = 0; it < 32; it++){
        int idx = it * TPB + t;                   // 4096 = 128x32
        int r = idx >> 5, c = idx & 31;
        float v = (ctaRow + r < B) ? z[(size_t)(ctaRow + r)*XD + c] : 0.f;
        __nv_bfloat16 h = __float2bfloat16(v);
        *(uint16_t*)(ZTp + r*66 + c*2) = *(uint16_t*)&h;
    }
    for (int idx = t; idx < 512; idx += TPB){
        int col = idx >> 4, p = idx & 15;
        *(uint32_t*)(MBp + col*64 + p*4) =
            pack_bf2(M[(2*p)*XD + col], M[(2*p+1)*XD + col]);
    }
    {   // o-state row t = x row (bf16)
        uint32_t* oxr = (uint32_t*)(OXp + t*80);
        if (active){
            #pragma unroll
            for (int q = 0; q < 4; q++){
                float4 v = *(const float4*)(x + (size_t)row*XD + 4*q);
                oxr[2*q]   = pack_bf2(v.x, v.y);
                oxr[2*q+1] = pack_bf2(v.z, v.w);
            }
        } else {
            #pragma unroll
            for (int q = 0; q < 8; q++) oxr[q] = 0u;
        }
    }
    __syncthreads();   // the ONLY cta-wide sync

    const int rg0 = wbase + g;        // m=0 rows: rg0, rg0+8
    const int rg1 = wbase + 16 + g;   // m=1 rows

    uint32_t A [2][8][4];   // fc output  (mlp1 input)
    uint32_t A2[2][8][4];   // mlp1 output (mlp2 input)

    for (int i = 0; i < XD; i++){
        // ---- M column i (broadcast LDS) ----
        uint32_t mb[16];
        #pragma unroll
        for (int p = 0; p < 16; p++) mb[p] = *(const uint32_t*)(MBp + i*64 + p*4);

        // ---- fc A-frags directly from OX ⊙ M (warp-local rows) ----
        uint32_t afc[2][2][4];
        #pragma unroll
        for (int m = 0; m < 2; m++){
            int rg = m ? rg1 : rg0;
            #pragma unroll
            for (int kk = 0; kk < 2; kk++){
                afc[m][kk][0] = hmul2u(*(const uint32_t*)(OXp + rg*80 + kk*32 + tq*4),          mb[8*kk+tq]);
                afc[m][kk][1] = hmul2u(*(const uint32_t*)(OXp + (rg+8)*80 + kk*32 + tq*4),      mb[8*kk+tq]);
                afc[m][kk][2] = hmul2u(*(const uint32_t*)(OXp + rg*80 + kk*32 + 16 + tq*4),     mb[8*kk+4+tq]);
                afc[m][kk][3] = hmul2u(*(const uint32_t*)(OXp + (rg+8)*80 + kk*32 + 16 + tq*4), mb[8*kk+4+tq]);
            }
        }

        float zf[2][2];
        #pragma unroll
        for (int m = 0; m < 2; m++){
            int rg = m ? rg1 : rg0;
            zf[m][0] = __bfloat162float(*(const __nv_bfloat16*)(ZTp + rg*66 + 2*i));
            zf[m][1] = __bfloat162float(*(const __nv_bfloat16*)(ZTp + (rg+8)*66 + 2*i));
        }

        // ================= fc (K=32), two j-halves, kk-outer =================
        #pragma unroll
        for (int h = 0; h < 2; h++){
            float C8[2][8][4];
            const uint2* wif = g_WiF + (size_t)i*16*2*32;
            #pragma unroll
            for (int kk = 0; kk < 2; kk++){
                uint2 w[8];
                #pragma unroll
                for (int jj = 0; jj < 8; jj++)
                    w[jj] = __ldg(&wif[((8*h+jj)*2 + kk)*32 + lane]);
                if (kk == 0){
                    #pragma unroll
                    for (int jj = 0; jj < 8; jj++){
                        mma_bf16_z(C8[0][jj], afc[0][0], w[jj].x, w[jj].y);
                        mma_bf16_z(C8[1][jj], afc[1][0], w[jj].x, w[jj].y);
                    }
                } else {
                    #pragma unroll
                    for (int jj = 0; jj < 8; jj++){
                        mma_bf16(C8[0][jj], afc[0][1], w[jj].x, w[jj].y);
                        mma_bf16(C8[1][jj], afc[1][1], w[jj].x, w[jj].y);
                    }
                }
            }
            // fc epilogue for jp = 4h..4h+3
            #pragma unroll
            for (int q = 0; q < 4; q++){
                int jp = 4*h + q;
                float2 blo = __ldg((const float2*)(bi + i*HD + 16*jp + 2*tq));
                float2 bhi = __ldg((const float2*)(bi + i*HD + 16*jp + 8 + 2*tq));
                float2 wlo = __ldg((const float2*)(g_w32 + i*HD + 16*jp + 2*tq));
                float2 whi = __ldg((const float2*)(g_w32 + i*HD + 16*jp + 8 + 2*tq));
                #pragma unroll
                for (int m = 0; m < 2; m++){
                    float t00 = fmaf(zf[m][0], wlo.x, blo.x);
                    float t01 = fmaf(zf[m][0], wlo.y, blo.y);
                    float t10 = fmaf(zf[m][1], wlo.x, blo.x);
                    float t11 = fmaf(zf[m][1], wlo.y, blo.y);
                    float u00 = fmaf(zf[m][0], whi.x, bhi.x);
                    float u01 = fmaf(zf[m][0], whi.y, bhi.y);
                    float u10 = fmaf(zf[m][1], whi.x, bhi.x);
                    float u11 = fmaf(zf[m][1], whi.y, bhi.y);
                    const float* c0 = C8[m][2*q];
                    const float* c1 = C8[m][2*q+1];
                    A[m][jp][0] = pack_bf2(fmaxf(c0[0]+t00,0.f), fmaxf(c0[1]+t01,0.f));
                    A[m][jp][1] = pack_bf2(fmaxf(c0[2]+t10,0.f), fmaxf(c0[3]+t11,0.f));
                    A[m][jp][2] = pack_bf2(fmaxf(c1[0]+u00,0.f), fmaxf(c1[1]+u01,0.f));
                    A[m][jp][3] = pack_bf2(fmaxf(c1[2]+u10,0.f), fmaxf(c1[3]+u11,0.f));
                }
            }
        }

        // ================= MLP1 (W1, K=128), j-halves, kkp-outer =============
        #pragma unroll
        for (int h = 0; h < 2; h++){
            float C8[2][8][4];
            #pragma unroll
            for (int kkp = 0; kkp < 4; kkp++){
                uint4 bv[8];
                #pragma unroll
                for (int jj = 0; jj < 8; jj++)
                    bv[jj] = __ldg(&g_W1F[((8*h+jj)*4 + kkp)*32 + lane]);
                // pass 1: a-even (k = 32*kkp .. +15), 16 independent C targets
                if (kkp == 0){
                    #pragma unroll
                    for (int jj = 0; jj < 8; jj++){
                        mma_bf16_z(C8[0][jj], A[0][0], bv[jj].x, bv[jj].y);
                        mma_bf16_z(C8[1][jj], A[1][0], bv[jj].x, bv[jj].y);
                    }
                } else {
                    #pragma unroll
                    for (int jj = 0; jj < 8; jj++){
                        mma_bf16(C8[0][jj], A[0][2*kkp], bv[jj].x, bv[jj].y);
                        mma_bf16(C8[1][jj], A[1][2*kkp], bv[jj].x, bv[jj].y);
                    }
                }
                // pass 2: a-odd (k = 32*kkp+16 .. +31)
                #pragma unroll
                for (int jj = 0; jj < 8; jj++){
                    mma_bf16(C8[0][jj], A[0][2*kkp+1], bv[jj].z, bv[jj].w);
                    mma_bf16(C8[1][jj], A[1][2*kkp+1], bv[jj].z, bv[jj].w);
                }
            }
            // epilogue with b1 -> A2
            #pragma unroll
            for (int q = 0; q < 4; q++){
                int jp = 4*h + q;
                float2 blo = __ldg((const float2*)(b1 + 16*jp + 2*tq));
                float2 bhi = __ldg((const float2*)(b1 + 16*jp + 8 + 2*tq));
                #pragma unroll
                for (int m = 0; m < 2; m++){
                    const float* c0 = C8[m][2*q];
                    const float* c1 = C8[m][2*q+1];
                    A2[m][jp][0] = pack_bf2(fmaxf(c0[0]+blo.x,0.f), fmaxf(c0[1]+blo.y,0.f));
                    A2[m][jp][1] = pack_bf2(fmaxf(c0[2]+blo.x,0.f), fmaxf(c0[3]+blo.y,0.f));
                    A2[m][jp][2] = pack_bf2(fmaxf(c1[0]+bhi.x,0.f), fmaxf(c1[1]+bhi.y,0.f));
                    A2[m][jp][3] = pack_bf2(fmaxf(c1[2]+bhi.x,0.f), fmaxf(c1[3]+bhi.y,0.f));
                }
            }
        }

        // ================= MLP2 (W2, K=128) + final dot, j-halves ============
        float p0[2] = {0.f, 0.f}, p1[2] = {0.f, 0.f};
        #pragma unroll
        for (int h = 0; h < 2; h++){
            float C8[2][8][4];
            #pragma unroll
            for (int kkp = 0; kkp < 4; kkp++){
                uint4 bv[8];
                #pragma unroll
                for (int jj = 0; jj < 8; jj++)
                    bv[jj] = __ldg(&g_W2F[((8*h+jj)*4 + kkp)*32 + lane]);
                if (kkp == 0){
                    #pragma unroll
                    for (int jj = 0; jj < 8; jj++){
                        mma_bf16_z(C8[0][jj], A2[0][0], bv[jj].x, bv[jj].y);
                        mma_bf16_z(C8[1][jj], A2[1][0], bv[jj].x, bv[jj].y);
                    }
                } else {
                    #pragma unroll
                    for (int jj = 0; jj < 8; jj++){
                        mma_bf16(C8[0][jj], A2[0][2*kkp], bv[jj].x, bv[jj].y);
                        mma_bf16(C8[1][jj], A2[1][2*kkp], bv[jj].x, bv[jj].y);
                    }
                }
                #pragma unroll
                for (int jj = 0; jj < 8; jj++){
                    mma_bf16(C8[0][jj], A2[0][2*kkp+1], bv[jj].z, bv[jj].w);
                    mma_bf16(C8[1][jj], A2[1][2*kkp+1], bv[jj].z, bv[jj].w);
                }
            }
            // final-dot partial for this half
            #pragma unroll
            for (int jj = 0; jj < 8; jj++){
                int j = 8*h + jj;
                float2 b2v = __ldg((const float2*)(b2 + 8*j + 2*tq));
                float2 wfv = __ldg((const float2*)(wf + i*HD + 8*j + 2*tq));
                #pragma unroll
                for (int m = 0; m < 2; m++){
                    p0[m] += fmaxf(C8[m][jj][0]+b2v.x, 0.f)*wfv.x
                           + fmaxf(C8[m][jj][1]+b2v.y, 0.f)*wfv.y;
                    p1[m] += fmaxf(C8[m][jj][2]+b2v.x, 0.f)*wfv.x
                           + fmaxf(C8[m][jj][3]+b2v.y, 0.f)*wfv.y;
                }
            }
        }

        // ---- sigmoid, state + out update ----
        {
            float bfv = __ldg(bf + i);
            #pragma unroll
            for (int m = 0; m < 2; m++){
                float q0 = p0[m], q1 = p1[m];
                q0 += __shfl_xor_sync(0xFFFFFFFFu, q0, 1);
                q0 += __shfl_xor_sync(0xFFFFFFFFu, q0, 2);
                q1 += __shfl_xor_sync(0xFFFFFFFFu, q1, 1);
                q1 += __shfl_xor_sync(0xFFFFFFFFu, q1, 2);
                if (tq == 0){
                    int lr0 = (m ? rg1 : rg0);
                    int lr1 = lr0 + 8;
                    float v0 = 1.f/(1.f + __expf(-(q0 + bfv)));
                    float v1 = 1.f/(1.f + __expf(-(q1 + bfv)));
                    __nv_bfloat16 h0 = __float2bfloat16(v0);
                    __nv_bfloat16 h1 = __float2bfloat16(v1);
                    *(uint16_t*)(OXp + lr0*80 + 2*i) = *(uint16_t*)&h0;
                    *(uint16_t*)(OXp + lr1*80 + 2*i) = *(uint16_t*)&h1;
                    int gr0 = ctaRow + lr0, gr1 = ctaRow + lr1;
                    if (gr0 < B) out[(size_t)gr0*XD + i] = v0;
                    if (gr1 < B) out[(size_t)gr1*XD + i] = v1;
                }
            }
        }
        __syncwarp();   // OX writes visible to this warp's next-step A-frag loads
    }
}

extern "C" void kernel_launch(void* const* d_in, const int* in_sizes, int n_in,
                              void* d_out, int out_size) {
    const float* x  = (const float*)d_in[0];
    const float* z  = (const float*)d_in[1];
    const float* M  = (const float*)d_in[2];
    const float* Wi = (const float*)d_in[3];
    const float* bi = (const float*)d_in[4];
    const float* wf = (const float*)d_in[5];
    const float* bf = (const float*)d_in[6];
    const float* W1 = (const float*)d_in[7];
    const float* b1 = (const float*)d_in[8];
    const float* W2 = (const float*)d_in[9];
    const float* b2 = (const float*)d_in[10];
    float* out = (float*)d_out;

    const int B = in_sizes[0] / XD;

    prep_frag<<<128, 256>>>(Wi, W1, W2);

    cudaFuncSetAttribute(gen_causal_nf,
                         cudaFuncAttributeMaxDynamicSharedMemorySize, SMEM_BYTES);
    const int grid = (B + ROWS - 1) / ROWS;
    gen_causal_nf<<<grid, TPB, SMEM_BYTES>>>(x, z, M, bi, wf, bf,
                                             b1, b2, out, B);
}